// round 5
// baseline (speedup 1.0000x reference)
#include <cuda_runtime.h>

#define N_NODES  100000
#define N_EDGES  2500000
#define N_GRAPHS 512
#define IN_DIM   14
#define HID      32

// ---------------- device scratch (float4-typed => 16B aligned, no runtime alloc) ----
__device__ float4 d_x4[N_NODES * 4];        // x padded 14 -> 16 floats
__device__ float4 d_agg4[N_NODES * 8];      // aggregation buffer (HID floats / node)
__device__ float4 d_h0v[N_NODES * 8];
__device__ float4 d_h1v[N_NODES * 8];
__device__ float4 d_pool4[N_GRAPHS * 8];

// Vectorized no-return global reduction (sm_90+): one LTS op for 16 bytes.
__device__ __forceinline__ void red_add_v4(float4* p, float4 v) {
    asm volatile("red.global.add.v4.f32 [%0], {%1,%2,%3,%4};"
                 :: "l"(p), "f"(v.x), "f"(v.y), "f"(v.z), "f"(v.w)
                 : "memory");
}

// ---------------- prep ----------------
__global__ void k_prep_x(const float* __restrict__ x) {
    int i = blockIdx.x * blockDim.x + threadIdx.x;
    if (i < N_NODES) {
        float buf[16];
        #pragma unroll
        for (int k = 0; k < IN_DIM; k++) buf[k] = x[i * IN_DIM + k];
        buf[14] = 0.0f; buf[15] = 0.0f;
        #pragma unroll
        for (int k = 0; k < 4; k++)
            d_x4[i * 4 + k] = make_float4(buf[4*k], buf[4*k+1], buf[4*k+2], buf[4*k+3]);
        float4 z = make_float4(0.f, 0.f, 0.f, 0.f);
        #pragma unroll
        for (int k = 0; k < 8; k++) d_agg4[i * 8 + k] = z;
    }
    if (i < N_GRAPHS * 8) d_pool4[i] = make_float4(0.f, 0.f, 0.f, 0.f);
}

// ---------------- layer-1 scatter: 4 threads/edge over 16 padded dims ----------------
// edge_index is int32: ei[0..N_EDGES) = src, ei[N_EDGES..2*N_EDGES) = dst
__global__ void k_scatter16(const int* __restrict__ ei) {
    int t = blockIdx.x * blockDim.x + threadIdx.x;
    if (t >= 4 * N_EDGES) return;
    int e = t >> 2, c = t & 3;
    int s = ei[e], d = ei[N_EDGES + e];
    float4 v = d_x4[s * 4 + c];
    red_add_v4(&d_agg4[d * 8 + c], v);   // first 4 float4 slots of the 32-float row
}

// ---------------- layer-1 update: h0 = relu(agg@Wrel1 + b + x@Wroot1); zero agg ----
__global__ void k_update1(const float* __restrict__ Wrel,
                          const float* __restrict__ brel,
                          const float* __restrict__ Wroot) {
    __shared__ float sWrel[IN_DIM * HID], sWroot[IN_DIM * HID], sb[HID];
    for (int k = threadIdx.x; k < IN_DIM * HID; k += blockDim.x) {
        sWrel[k]  = Wrel[k];
        sWroot[k] = Wroot[k];
    }
    if (threadIdx.x < HID) sb[threadIdx.x] = brel[threadIdx.x];
    __syncthreads();

    int n = blockIdx.x * blockDim.x + threadIdx.x;
    if (n >= N_NODES) return;

    float xa[16], ag[16];
    #pragma unroll
    for (int k = 0; k < 4; k++) {
        float4 vx = d_x4[n * 4 + k];
        float4 va = d_agg4[n * 8 + k];
        xa[4*k] = vx.x; xa[4*k+1] = vx.y; xa[4*k+2] = vx.z; xa[4*k+3] = vx.w;
        ag[4*k] = va.x; ag[4*k+1] = va.y; ag[4*k+2] = va.z; ag[4*k+3] = va.w;
    }
    // re-zero agg row for next layer's scatter
    float4 z = make_float4(0.f, 0.f, 0.f, 0.f);
    #pragma unroll
    for (int k = 0; k < 8; k++) d_agg4[n * 8 + k] = z;

    float* h0 = (float*)d_h0v;
    for (int j = 0; j < HID; j++) {
        float acc = sb[j];
        #pragma unroll
        for (int k = 0; k < IN_DIM; k++)
            acc += ag[k] * sWrel[k * HID + j] + xa[k] * sWroot[k * HID + j];
        h0[n * HID + j] = fmaxf(acc, 0.0f);
    }
}

// ---------------- 32-dim scatter: 8 threads/edge, float4 gather + v4 red ----------
__global__ void k_scatter32(const int* __restrict__ ei, int src_is_h0) {
    int t = blockIdx.x * blockDim.x + threadIdx.x;
    if (t >= 8 * N_EDGES) return;
    const float4* h = src_is_h0 ? d_h0v : d_h1v;
    int e = t >> 3, c = t & 7;
    int s = ei[e], d = ei[N_EDGES + e];
    float4 v = h[s * 8 + c];
    red_add_v4(&d_agg4[d * 8 + c], v);
}

// ---------------- 32-dim update: hout = relu(agg@Wrel + b + hin@Wroot); zero agg --
__global__ void k_update32(int src_is_h0,
                           const float* __restrict__ Wrel,
                           const float* __restrict__ brel,
                           const float* __restrict__ Wroot) {
    __shared__ float sWrel[HID * HID], sWroot[HID * HID], sb[HID];
    for (int k = threadIdx.x; k < HID * HID; k += blockDim.x) {
        sWrel[k]  = Wrel[k];
        sWroot[k] = Wroot[k];
    }
    if (threadIdx.x < HID) sb[threadIdx.x] = brel[threadIdx.x];
    __syncthreads();

    int n = blockIdx.x * blockDim.x + threadIdx.x;
    if (n >= N_NODES) return;

    const float* hin = src_is_h0 ? (const float*)d_h0v : (const float*)d_h1v;
    float*      hout = src_is_h0 ? (float*)d_h1v       : (float*)d_h0v;

    float hh[HID], ag[HID];
    #pragma unroll
    for (int k = 0; k < 8; k++) {
        float4 va = d_agg4[n * 8 + k];
        ag[4*k] = va.x; ag[4*k+1] = va.y; ag[4*k+2] = va.z; ag[4*k+3] = va.w;
    }
    #pragma unroll
    for (int k = 0; k < HID; k++) hh[k] = hin[n * HID + k];

    float4 z = make_float4(0.f, 0.f, 0.f, 0.f);
    #pragma unroll
    for (int k = 0; k < 8; k++) d_agg4[n * 8 + k] = z;

    for (int j = 0; j < HID; j++) {
        float acc = sb[j];
        #pragma unroll
        for (int k = 0; k < HID; k++)
            acc += ag[k] * sWrel[k * HID + j] + hh[k] * sWroot[k * HID + j];
        hout[n * HID + j] = fmaxf(acc, 0.0f);
    }
}

// ---------------- sum-pool per graph ----------------
__global__ void k_pool(int src_is_h0, const int* __restrict__ batch) {
    int t = blockIdx.x * blockDim.x + threadIdx.x;
    if (t >= 8 * N_NODES) return;
    const float4* h = src_is_h0 ? d_h0v : d_h1v;
    int n = t >> 3, c = t & 7;
    int g = batch[n];
    float4 v = h[n * 8 + c];
    red_add_v4(&d_pool4[g * 8 + c], v);
}

// ---------------- MLP head + log_softmax ----------------
__global__ void k_head(const float* __restrict__ lin1w, const float* __restrict__ lin1b,
                       const float* __restrict__ lin2w, const float* __restrict__ lin2b,
                       float* __restrict__ out) {
    __shared__ float s1[HID * HID], sb1[HID], s2[HID * 2], sb2[2];
    for (int k = threadIdx.x; k < HID * HID; k += blockDim.x) s1[k] = lin1w[k];
    if (threadIdx.x < HID)     sb1[threadIdx.x] = lin1b[threadIdx.x];
    if (threadIdx.x < HID * 2) s2[threadIdx.x]  = lin2w[threadIdx.x];
    if (threadIdx.x < 2)       sb2[threadIdx.x] = lin2b[threadIdx.x];
    __syncthreads();

    int g = threadIdx.x;  // one block of N_GRAPHS threads
    if (g >= N_GRAPHS) return;

    const float* pool = (const float*)d_pool4;
    float gr[HID];
    #pragma unroll
    for (int k = 0; k < HID; k++) gr[k] = pool[g * HID + k];

    float hid[HID];
    for (int j = 0; j < HID; j++) {
        float acc = sb1[j];
        #pragma unroll
        for (int k = 0; k < HID; k++) acc += gr[k] * s1[k * HID + j];
        hid[j] = fmaxf(acc, 0.0f);
    }
    float l0 = sb2[0], l1 = sb2[1];
    #pragma unroll
    for (int k = 0; k < HID; k++) {
        l0 += hid[k] * s2[k * 2 + 0];
        l1 += hid[k] * s2[k * 2 + 1];
    }
    float m   = fmaxf(l0, l1);
    float lse = m + logf(expf(l0 - m) + expf(l1 - m));
    out[g * 2 + 0] = l0 - lse;
    out[g * 2 + 1] = l1 - lse;
}

// ---------------- launch: inputs identified BY ELEMENT COUNT (order-agnostic) -------
// Element counts: x=1400000, W_rel1=448, b_rel1=32, W_root1=448, W_rel=4096,
//   b_rel=128, W_root=4096, lin1_w=1024, lin1_b=32, lin2_w=64, lin2_b=2,
//   edge_index=5000000 (int32!), batch=100000 (int32!).
// Ties (448, 4096, 32): first occurrence in declaration order is
// W_rel1 / W_rel / b_rel1 respectively (holds for dict order and name-sort).
extern "C" void kernel_launch(void* const* d_in, const int* in_sizes, int n_in,
                              void* d_out, int out_size) {
    const float *x = 0, *Wrel1 = 0, *brel1 = 0, *Wroot1 = 0;
    const float *Wrel = 0, *brel = 0, *Wroot = 0;
    const float *lin1w = 0, *lin1b = 0, *lin2w = 0, *lin2b = 0;
    const int *ei = 0, *batch = 0;

    for (int i = 0; i < n_in; i++) {
        int sz = in_sizes[i];
        const void* p = d_in[i];
        switch (sz) {
            case 1400000: x      = (const float*)p; break;
            case 5000000: ei     = (const int*)p; break;
            case 100000:  batch  = (const int*)p; break;
            case 448:     if (!Wrel1) Wrel1 = (const float*)p; else Wroot1 = (const float*)p; break;
            case 4096:    if (!Wrel)  Wrel  = (const float*)p; else Wroot  = (const float*)p; break;
            case 32:      if (!brel1) brel1 = (const float*)p; else lin1b  = (const float*)p; break;
            case 128:     brel   = (const float*)p; break;
            case 1024:    lin1w  = (const float*)p; break;
            case 64:      lin2w  = (const float*)p; break;
            case 2:       lin2b  = (const float*)p; break;
            default: break;
        }
    }
    float* out = (float*)d_out;

    const int TB = 256;
    k_prep_x<<<(N_NODES + TB - 1) / TB, TB>>>(x);

    // layer 1 (IN_DIM=14 padded to 16)
    k_scatter16<<<(4 * N_EDGES + TB - 1) / TB, TB>>>(ei);
    k_update1<<<(N_NODES + TB - 1) / TB, TB>>>(Wrel1, brel1, Wroot1);

    // layers 2..5 : ping-pong h0 <-> h1 via parity flag
    int src_is_h0 = 1;
    for (int i = 0; i < 4; i++) {
        k_scatter32<<<(8 * N_EDGES + TB - 1) / TB, TB>>>(ei, src_is_h0);
        k_update32<<<(N_NODES + TB - 1) / TB, TB>>>(
            src_is_h0,
            Wrel  + i * HID * HID,
            brel  + i * HID,
            Wroot + i * HID * HID);
        src_is_h0 ^= 1;
    }

    k_pool<<<(8 * N_NODES + TB - 1) / TB, TB>>>(src_is_h0, batch);
    k_head<<<1, N_GRAPHS>>>(lin1w, lin1b, lin2w, lin2b, out);
}

// round 6
// speedup vs baseline: 1.0150x; 1.0150x over previous
#include <cuda_runtime.h>

#define N_NODES  100000
#define N_EDGES  2500000
#define N_GRAPHS 512
#define IN_DIM   14
#define HID      32

// ---------------- device scratch ----------------
__device__ float4 d_x4[N_NODES * 4];        // x padded 14 -> 16 floats
__device__ float4 d_h0v[N_NODES * 8];
__device__ float4 d_h1v[N_NODES * 8];
__device__ float4 d_pool4[N_GRAPHS * 8];
__device__ int    d_deg[N_NODES];           // degree, then reused as fill cursor
__device__ int    d_off[N_NODES + 1];       // CSR row offsets (by dst)
__device__ int    d_csrc[N_EDGES];          // CSR column = src node of each edge

__device__ __forceinline__ void red_add_v4(float4* p, float4 v) {
    asm volatile("red.global.add.v4.f32 [%0], {%1,%2,%3,%4};"
                 :: "l"(p), "f"(v.x), "f"(v.y), "f"(v.z), "f"(v.w)
                 : "memory");
}

// ---------------- prep: pad x, zero deg + pool ----------------
__global__ void k_prep(const float* __restrict__ x) {
    int i = blockIdx.x * blockDim.x + threadIdx.x;
    if (i < N_NODES) {
        float buf[16];
        #pragma unroll
        for (int k = 0; k < IN_DIM; k++) buf[k] = x[i * IN_DIM + k];
        buf[14] = 0.0f; buf[15] = 0.0f;
        #pragma unroll
        for (int k = 0; k < 4; k++)
            d_x4[i * 4 + k] = make_float4(buf[4*k], buf[4*k+1], buf[4*k+2], buf[4*k+3]);
        d_deg[i] = 0;
    }
    if (i < N_GRAPHS * 8) d_pool4[i] = make_float4(0.f, 0.f, 0.f, 0.f);
}

// ---------------- CSR build: histogram over dst ----------------
__global__ void k_hist(const int* __restrict__ ei) {
    int i = blockIdx.x * blockDim.x + threadIdx.x;
    if (i < N_EDGES) atomicAdd(&d_deg[ei[N_EDGES + i]], 1);
}

// ---------------- CSR build: exclusive scan (single block, 1024 threads) ----------
__global__ void k_scan() {
    const int C = (N_NODES + 1023) / 1024;  // 98
    __shared__ int sPart[1024];
    int t = threadIdx.x;
    int start = t * C;
    int sum = 0;
    for (int i = 0; i < C; i++) {
        int idx = start + i;
        if (idx < N_NODES) sum += d_deg[idx];
    }
    sPart[t] = sum;
    __syncthreads();
    for (int off = 1; off < 1024; off <<= 1) {
        int v = (t >= off) ? sPart[t - off] : 0;
        __syncthreads();
        sPart[t] += v;
        __syncthreads();
    }
    int run = (t == 0) ? 0 : sPart[t - 1];
    for (int i = 0; i < C; i++) {
        int idx = start + i;
        if (idx < N_NODES) {
            int d = d_deg[idx];
            d_off[idx] = run;
            d_deg[idx] = run;   // becomes the fill cursor
            run += d;
        }
    }
    if (t == 0) d_off[N_NODES] = N_EDGES;
}

// ---------------- CSR build: scatter src ids into dst-sorted order ----------------
__global__ void k_fill(const int* __restrict__ ei) {
    int i = blockIdx.x * blockDim.x + threadIdx.x;
    if (i < N_EDGES) {
        int s = ei[i], d = ei[N_EDGES + i];
        int pos = atomicAdd(&d_deg[d], 1);
        d_csrc[pos] = s;
    }
}

// ---------------- layer 1: warp/node CSR gather + fused update (IN=14) ------------
// h0[n] = relu( (sum_{s in N(n)} x[s]) @ Wrel1 + b + x[n] @ Wroot1 )
__global__ void __launch_bounds__(512) k_conv1(const float* __restrict__ Wrel,
                                               const float* __restrict__ brel,
                                               const float* __restrict__ Wroot) {
    __shared__ float sW[IN_DIM * HID], sWr[IN_DIM * HID], sb[HID];
    __shared__ float sAgg[16][16], sHin[16][16];
    for (int k = threadIdx.x; k < IN_DIM * HID; k += blockDim.x) {
        sW[k]  = Wrel[k];
        sWr[k] = Wroot[k];
    }
    if (threadIdx.x < HID) sb[threadIdx.x] = brel[threadIdx.x];
    __syncthreads();

    const float* xp = (const float*)d_x4;   // padded rows of 16
    float* h0 = (float*)d_h0v;
    int lane = threadIdx.x & 31, w = threadIdx.x >> 5;
    int warpId = blockIdx.x * (blockDim.x >> 5) + w;
    int nWarps = gridDim.x * (blockDim.x >> 5);

    for (int n = warpId; n < N_NODES; n += nWarps) {
        int beg = d_off[n], end = d_off[n + 1];
        float a0 = 0.f, a1 = 0.f;
        for (int base = beg; base < end; base += 32) {
            int cnt = end - base; if (cnt > 32) cnt = 32;
            int sidx = (base + lane < end) ? d_csrc[base + lane] : 0;
            int j = 0;
            for (; j + 2 <= cnt; j += 2) {
                int s0 = __shfl_sync(0xffffffff, sidx, j);
                int s1 = __shfl_sync(0xffffffff, sidx, j + 1);
                if (lane < 16) {
                    a0 += xp[s0 * 16 + lane];
                    a1 += xp[s1 * 16 + lane];
                }
            }
            if (j < cnt) {
                int s0 = __shfl_sync(0xffffffff, sidx, j);
                if (lane < 16) a0 += xp[s0 * 16 + lane];
            }
        }
        if (lane < 16) {
            sAgg[w][lane] = a0 + a1;
            sHin[w][lane] = xp[n * 16 + lane];
        }
        __syncwarp();
        float o = sb[lane];
        #pragma unroll
        for (int k = 0; k < IN_DIM; k++)
            o += sAgg[w][k] * sW[k * HID + lane] + sHin[w][k] * sWr[k * HID + lane];
        h0[n * HID + lane] = fmaxf(o, 0.0f);
        __syncwarp();
    }
}

// ---------------- layers 2..5: warp/node CSR gather + fused update (32-dim) --------
__global__ void __launch_bounds__(512) k_conv32(int src_is_h0,
                                                const float* __restrict__ Wrel,
                                                const float* __restrict__ brel,
                                                const float* __restrict__ Wroot) {
    __shared__ float sW[HID * HID], sWr[HID * HID], sb[HID];
    __shared__ float sAgg[16][HID], sHin[16][HID];
    for (int k = threadIdx.x; k < HID * HID; k += blockDim.x) {
        sW[k]  = Wrel[k];
        sWr[k] = Wroot[k];
    }
    if (threadIdx.x < HID) sb[threadIdx.x] = brel[threadIdx.x];
    __syncthreads();

    const float* hin = src_is_h0 ? (const float*)d_h0v : (const float*)d_h1v;
    float*      hout = src_is_h0 ? (float*)d_h1v       : (float*)d_h0v;

    int lane = threadIdx.x & 31, w = threadIdx.x >> 5;
    int warpId = blockIdx.x * (blockDim.x >> 5) + w;
    int nWarps = gridDim.x * (blockDim.x >> 5);

    for (int n = warpId; n < N_NODES; n += nWarps) {
        int beg = d_off[n], end = d_off[n + 1];
        float a0 = 0.f, a1 = 0.f, a2 = 0.f, a3 = 0.f;
        for (int base = beg; base < end; base += 32) {
            int cnt = end - base; if (cnt > 32) cnt = 32;
            int sidx = (base + lane < end) ? d_csrc[base + lane] : 0;
            int j = 0;
            for (; j + 4 <= cnt; j += 4) {
                int s0 = __shfl_sync(0xffffffff, sidx, j);
                int s1 = __shfl_sync(0xffffffff, sidx, j + 1);
                int s2 = __shfl_sync(0xffffffff, sidx, j + 2);
                int s3 = __shfl_sync(0xffffffff, sidx, j + 3);
                a0 += hin[s0 * HID + lane];
                a1 += hin[s1 * HID + lane];
                a2 += hin[s2 * HID + lane];
                a3 += hin[s3 * HID + lane];
            }
            for (; j < cnt; j++) {
                int s0 = __shfl_sync(0xffffffff, sidx, j);
                a0 += hin[s0 * HID + lane];
            }
        }
        sAgg[w][lane] = (a0 + a1) + (a2 + a3);
        sHin[w][lane] = hin[n * HID + lane];
        __syncwarp();
        float o = sb[lane];
        #pragma unroll
        for (int k = 0; k < HID; k++)
            o += sAgg[w][k] * sW[k * HID + lane] + sHin[w][k] * sWr[k * HID + lane];
        hout[n * HID + lane] = fmaxf(o, 0.0f);
        __syncwarp();
    }
}

// ---------------- sum-pool per graph ----------------
__global__ void k_pool(int src_is_h0, const int* __restrict__ batch) {
    int t = blockIdx.x * blockDim.x + threadIdx.x;
    if (t >= 8 * N_NODES) return;
    const float4* h = src_is_h0 ? d_h0v : d_h1v;
    int n = t >> 3, c = t & 7;
    int g = batch[n];
    float4 v = h[n * 8 + c];
    red_add_v4(&d_pool4[g * 8 + c], v);
}

// ---------------- MLP head + log_softmax ----------------
__global__ void k_head(const float* __restrict__ lin1w, const float* __restrict__ lin1b,
                       const float* __restrict__ lin2w, const float* __restrict__ lin2b,
                       float* __restrict__ out) {
    __shared__ float s1[HID * HID], sb1[HID], s2[HID * 2], sb2[2];
    for (int k = threadIdx.x; k < HID * HID; k += blockDim.x) s1[k] = lin1w[k];
    if (threadIdx.x < HID)     sb1[threadIdx.x] = lin1b[threadIdx.x];
    if (threadIdx.x < HID * 2) s2[threadIdx.x]  = lin2w[threadIdx.x];
    if (threadIdx.x < 2)       sb2[threadIdx.x] = lin2b[threadIdx.x];
    __syncthreads();

    int g = threadIdx.x;
    if (g >= N_GRAPHS) return;

    const float* pool = (const float*)d_pool4;
    float gr[HID];
    #pragma unroll
    for (int k = 0; k < HID; k++) gr[k] = pool[g * HID + k];

    float hid[HID];
    for (int j = 0; j < HID; j++) {
        float acc = sb1[j];
        #pragma unroll
        for (int k = 0; k < HID; k++) acc += gr[k] * s1[k * HID + j];
        hid[j] = fmaxf(acc, 0.0f);
    }
    float l0 = sb2[0], l1 = sb2[1];
    #pragma unroll
    for (int k = 0; k < HID; k++) {
        l0 += hid[k] * s2[k * 2 + 0];
        l1 += hid[k] * s2[k * 2 + 1];
    }
    float m   = fmaxf(l0, l1);
    float lse = m + logf(expf(l0 - m) + expf(l1 - m));
    out[g * 2 + 0] = l0 - lse;
    out[g * 2 + 1] = l1 - lse;
}

// ---------------- launch: inputs identified BY ELEMENT COUNT (order-agnostic) -------
extern "C" void kernel_launch(void* const* d_in, const int* in_sizes, int n_in,
                              void* d_out, int out_size) {
    const float *x = 0, *Wrel1 = 0, *brel1 = 0, *Wroot1 = 0;
    const float *Wrel = 0, *brel = 0, *Wroot = 0;
    const float *lin1w = 0, *lin1b = 0, *lin2w = 0, *lin2b = 0;
    const int *ei = 0, *batch = 0;

    for (int i = 0; i < n_in; i++) {
        int sz = in_sizes[i];
        const void* p = d_in[i];
        switch (sz) {
            case 1400000: x      = (const float*)p; break;
            case 5000000: ei     = (const int*)p; break;
            case 100000:  batch  = (const int*)p; break;
            case 448:     if (!Wrel1) Wrel1 = (const float*)p; else Wroot1 = (const float*)p; break;
            case 4096:    if (!Wrel)  Wrel  = (const float*)p; else Wroot  = (const float*)p; break;
            case 32:      if (!brel1) brel1 = (const float*)p; else lin1b  = (const float*)p; break;
            case 128:     brel   = (const float*)p; break;
            case 1024:    lin1w  = (const float*)p; break;
            case 64:      lin2w  = (const float*)p; break;
            case 2:       lin2b  = (const float*)p; break;
            default: break;
        }
    }
    float* out = (float*)d_out;

    const int TB = 256;
    const int CONV_BLOCKS = 592;   // 148 SMs * 4, 16 warps/block, grid-stride

    // prep + CSR build
    k_prep<<<(N_NODES + TB - 1) / TB, TB>>>(x);
    k_hist<<<(N_EDGES + TB - 1) / TB, TB>>>(ei);
    k_scan<<<1, 1024>>>();
    k_fill<<<(N_EDGES + TB - 1) / TB, TB>>>(ei);

    // layer 1
    k_conv1<<<CONV_BLOCKS, 512>>>(Wrel1, brel1, Wroot1);

    // layers 2..5 : ping-pong h0 <-> h1
    int src_is_h0 = 1;
    for (int i = 0; i < 4; i++) {
        k_conv32<<<CONV_BLOCKS, 512>>>(
            src_is_h0,
            Wrel  + i * HID * HID,
            brel  + i * HID,
            Wroot + i * HID * HID);
        src_is_h0 ^= 1;
    }

    // final h lives in h0 (src_is_h0 ended at 1)
    k_pool<<<(8 * N_NODES + TB - 1) / TB, TB>>>(src_is_h0, batch);
    k_head<<<1, N_GRAPHS>>>(lin1w, lin1b, lin2w, lin2b, out);
}